// round 8
// baseline (speedup 1.0000x reference)
#include <cuda_runtime.h>
#include <cstdint>

#define BATCH 4
#define SEQ   2048
#define DSEQ  1024
#define HEADS 16
#define DHEAD 64
#define DINNER 1024
#define MROWS (BATCH*SEQ)   // 8192
#define NQKV  (3*DINNER)    // 3072

__device__ float g_Q[BATCH * HEADS * SEQ * DHEAD];
__device__ float g_K[BATCH * HEADS * SEQ * DHEAD];
__device__ float g_V[BATCH * HEADS * SEQ * DHEAD];
__device__ float g_AO[MROWS * DINNER];

__device__ __forceinline__ float f2tf(float f) {
    unsigned u;
    asm("cvt.rna.tf32.f32 %0, %1;" : "=r"(u) : "f"(f));
    return __uint_as_float(u);
}
__device__ __forceinline__ void mma_tf32(float c[4],
                                         unsigned a0, unsigned a1, unsigned a2, unsigned a3,
                                         unsigned b0, unsigned b1) {
    asm volatile(
        "mma.sync.aligned.m16n8k8.row.col.f32.tf32.tf32.f32 "
        "{%0,%1,%2,%3},{%4,%5,%6,%7},{%8,%9},{%0,%1,%2,%3};"
        : "+f"(c[0]), "+f"(c[1]), "+f"(c[2]), "+f"(c[3])
        : "r"(a0), "r"(a1), "r"(a2), "r"(a3), "r"(b0), "r"(b1));
}
#define FB(x) __float_as_uint(x)

__device__ __forceinline__ unsigned smem_u32(const void* p) {
    unsigned a;
    asm("{ .reg .u64 t; cvta.to.shared.u64 t, %1; cvt.u32.u64 %0, t; }"
        : "=r"(a) : "l"(p));
    return a;
}
__device__ __forceinline__ void cp16(unsigned dst, const float* src) {
    asm volatile("cp.async.cg.shared.global [%0], [%1], 16;"
                 :: "r"(dst), "l"(src) : "memory");
}
#define CP_COMMIT() asm volatile("cp.async.commit_group;" ::: "memory")
#define CP_WAIT1()  asm volatile("cp.async.wait_group 1;" ::: "memory")

// fragment-pair column permutation: logical col d -> physical, so that
// (d, d+4) within each 8-group land adjacent (enables LDS.64 fragments)
__device__ __forceinline__ int cperm(int d) {
    return (d & ~7) | (((d & 3) << 1) | ((d >> 2) & 1));
}

// ---------------------------------------------------------------------
// GEMM: D = A[M,1024] @ B[N,1024]^T. BM=BN=128, BK=32, 8 warps (2m x 4n),
// warp tile 64x32. Row stride 36 (LDS.32 frags conflict-free: 4g+k+tg).
// 3-stage cp.async pipeline, one barrier per 32-k tile.
// mode 0: A = x, scatter to g_Q/g_K/g_V.  mode 1: A = g_AO, out = D + bias.
// ---------------------------------------------------------------------
#define KST 36
#define NSTG 3
#define STGF (128 * KST)             // 4608 floats per matrix per stage
#define GNIT 32                      // 1024 / 32
#define GEMM_SMEM_BYTES (2 * NSTG * STGF * 4)   // 110592

__device__ __forceinline__ void g_mma_k8(const float* As_, const float* Bs_,
                                         float c[4][4][4],
                                         int k, int wm, int wn, int g, int tg) {
    unsigned a[4][4], b[4][2];
#pragma unroll
    for (int mt = 0; mt < 4; mt++) {
        const float* ap = &As_[(wm * 64 + mt * 16 + g) * KST + k + tg];
        a[mt][0] = FB(f2tf(ap[0]));
        a[mt][1] = FB(f2tf(ap[8 * KST]));
        a[mt][2] = FB(f2tf(ap[4]));
        a[mt][3] = FB(f2tf(ap[8 * KST + 4]));
    }
#pragma unroll
    for (int nt = 0; nt < 4; nt++) {
        const float* bp = &Bs_[(wn * 32 + nt * 8 + g) * KST + k + tg];
        b[nt][0] = FB(f2tf(bp[0]));
        b[nt][1] = FB(f2tf(bp[4]));
    }
#pragma unroll
    for (int mt = 0; mt < 4; mt++)
#pragma unroll
        for (int nt = 0; nt < 4; nt++)
            mma_tf32(c[mt][nt], a[mt][0], a[mt][1], a[mt][2], a[mt][3],
                     b[nt][0], b[nt][1]);
}

__global__ __launch_bounds__(256, 2) void gemm_kernel(
    const float* __restrict__ Aarg, const float* __restrict__ B,
    const float* __restrict__ bias, float* __restrict__ out, int mode)
{
    extern __shared__ float smf[];
    float* As = smf;                 // NSTG stages
    float* Bs = smf + NSTG * STGF;

    const int t    = threadIdx.x;
    const int lane = t & 31;
    const int wp   = t >> 5;
    const int g    = lane >> 2;
    const int tg   = lane & 3;
    const int wm   = wp & 1;
    const int wn   = wp >> 1;
    const int m0   = blockIdx.y * 128;
    const int n0   = blockIdx.x * 128;

    const float* A = (mode == 1) ? (const float*)g_AO : Aarg;

    // loader: thread -> row t>>1, 16-float half (t&1)*16; 4 cp16 per matrix
    const int row  = t >> 1;
    const int half = (t & 1) * 16;
    const float* Ag = A + (size_t)(m0 + row) * 1024 + half;
    const float* Bg = B + (size_t)(n0 + row) * 1024 + half;
    const unsigned aOff = smem_u32(As) + (unsigned)(row * KST + half) * 4u;
    const unsigned bOff = smem_u32(Bs) + (unsigned)(row * KST + half) * 4u;

    // prologue: stages 0,1 in flight
#pragma unroll
    for (int s = 0; s < 2; s++) {
        const int k0 = s * 32;
        const unsigned so = (unsigned)(s * STGF) * 4u;
#pragma unroll
        for (int q = 0; q < 4; q++) {
            cp16(aOff + so + q * 16u, Ag + k0 + q * 4);
            cp16(bOff + so + q * 16u, Bg + k0 + q * 4);
        }
        CP_COMMIT();
    }

    float c[4][4][4] = {};
    int buf = 0;

    for (int it = 0; it < GNIT; it++) {
        CP_WAIT1();          // current stage complete
        __syncthreads();     // all warps done with the buffer being refilled
        if (it + 2 < GNIT) {
            const int k0 = (it + 2) * 32;
            int nb = buf + 1; if (nb == NSTG) nb = 0;
            nb = nb + 1; if (nb == NSTG) nb = 0;          // (buf+2)%3
            const unsigned so = (unsigned)(nb * STGF) * 4u;
#pragma unroll
            for (int q = 0; q < 4; q++) {
                cp16(aOff + so + q * 16u, Ag + k0 + q * 4);
                cp16(bOff + so + q * 16u, Bg + k0 + q * 4);
            }
        }
        CP_COMMIT();         // commit (possibly empty) to keep group count fixed
        const float* Ac = As + buf * STGF;
        const float* Bc = Bs + buf * STGF;
#pragma unroll
        for (int ks = 0; ks < 4; ks++)
            g_mma_k8(Ac, Bc, c, ks * 8, wm, wn, g, tg);
        if (++buf == NSTG) buf = 0;
    }

    if (mode == 0) {
#pragma unroll
        for (int mt = 0; mt < 4; mt++) {
#pragma unroll
            for (int nt = 0; nt < 4; nt++) {
                int col  = n0 + wn * 32 + nt * 8 + tg * 2;
                int part = col >> 10;
                int h    = (col >> 6) & 15;
                int d    = col & 63;
                float* Tp = (part == 0) ? g_Q : (part == 1) ? g_K : g_V;
                int m  = m0 + wm * 64 + mt * 16 + g;
                int b  = m >> 11, n = m & 2047;
                *(float2*)&Tp[(((size_t)(b * HEADS + h)) * SEQ + n) * DHEAD + d] =
                    make_float2(c[mt][nt][0], c[mt][nt][1]);
                int m2 = m + 8;
                int b2 = m2 >> 11, n2 = m2 & 2047;
                *(float2*)&Tp[(((size_t)(b2 * HEADS + h)) * SEQ + n2) * DHEAD + d] =
                    make_float2(c[mt][nt][2], c[mt][nt][3]);
            }
        }
    } else {
#pragma unroll
        for (int mt = 0; mt < 4; mt++) {
#pragma unroll
            for (int nt = 0; nt < 4; nt++) {
                int col = n0 + wn * 32 + nt * 8 + tg * 2;
                float bx = bias[col], by = bias[col + 1];
                int m = m0 + wm * 64 + mt * 16 + g;
                *(float2*)&out[(size_t)m * DSEQ + col] =
                    make_float2(c[mt][nt][0] + bx, c[mt][nt][1] + by);
                *(float2*)&out[(size_t)(m + 8) * DSEQ + col] =
                    make_float2(c[mt][nt][2] + bx, c[mt][nt][3] + by);
            }
        }
    }
}

// ---------------------------------------------------------------------
// Flash attention. Q-tile 128, KV-tile 64, 8 warps on m.
// Qs/Ks/Vs use column-PERMUTED layouts (cperm) with stride 72 so fragment
// pairs are adjacent: Q A-frag = 2 LDS.64, K/V B-frag = 1 LDS.64.
// Ps stays row-major stride 68 (unpermuted).
// ---------------------------------------------------------------------
#define QST 72
#define PST 68
#define ATTN_FLOATS (128 * QST + 64 * QST + 64 * QST + 128 * PST)
#define ATTN_SMEM_BYTES (ATTN_FLOATS * 4)   // 108544

__global__ __launch_bounds__(256, 2) void attn_kernel() {
    extern __shared__ float sm[];
    float* Qs = sm;                         // [128][QST] permuted cols (d)
    float* Ks = sm + 128 * QST;             // [64][QST]  permuted cols (d)
    float* Vs = sm + 192 * QST;             // [64][QST]  rows=d, permuted cols (j)
    float* Ps = sm + 256 * QST;             // [128][PST] natural

    const int t    = threadIdx.x;
    const int lane = t & 31;
    const int wp   = t >> 5;
    const int g    = lane >> 2;
    const int tg   = lane & 3;
    const int bh   = blockIdx.y;
    const int q0   = blockIdx.x * 128;

    const size_t base = (size_t)bh * SEQ * DHEAD;
    const float* Qg = g_Q + base;
    const float* Kg = g_K + base;
    const float* Vg = g_V + base;

    // ---- load Q tile into permuted layout, pre-scaled ----
    {
        int row = t >> 1, h0 = (t & 1) * 32;
        const float* src = Qg + (size_t)(q0 + row) * DHEAD + h0;
        float* dst = &Qs[row * QST];
#pragma unroll
        for (int i = 0; i < 8; i++) {
            float4 v = *(const float4*)(src + i * 4);
            int d0 = h0 + i * 4;
            dst[cperm(d0 + 0)] = f2tf(v.x * 0.125f);
            dst[cperm(d0 + 1)] = f2tf(v.y * 0.125f);
            dst[cperm(d0 + 2)] = f2tf(v.z * 0.125f);
            dst[cperm(d0 + 3)] = f2tf(v.w * 0.125f);
        }
    }

    const int j   = t >> 2;          // 0..63
    const int seg = (t & 3) * 16;
    const int pj  = cperm(j);        // permuted column for V^T store

    float4 pk[4], pv[4];
    {
        const float* ksrc = Kg + (size_t)j * DHEAD + seg;
        const float* vsrc = Vg + (size_t)j * DHEAD + seg;
#pragma unroll
        for (int i = 0; i < 4; i++) {
            pk[i] = *(const float4*)(ksrc + i * 4);
            pv[i] = *(const float4*)(vsrc + i * 4);
        }
    }

    float mi[2] = {-1e30f, -1e30f};
    float li[2] = {0.f, 0.f};
    float of[8][4] = {};

    for (int kv0 = 0; kv0 < SEQ; kv0 += 64) {
        // ---- store prefetched K (permuted d cols) / V^T (permuted j cols) ----
        {
            float* kd = &Ks[j * QST];
#pragma unroll
            for (int i = 0; i < 4; i++) {
                int d0 = seg + i * 4;
                float e[4] = {pk[i].x, pk[i].y, pk[i].z, pk[i].w};
                float v[4] = {pv[i].x, pv[i].y, pv[i].z, pv[i].w};
#pragma unroll
                for (int ee = 0; ee < 4; ee++) {
                    kd[cperm(d0 + ee)] = f2tf(e[ee]);
                    Vs[(d0 + ee) * QST + pj] = f2tf(v[ee]);
                }
            }
        }
        __syncthreads();

        // ---- S = Q K^T ----
        float sc[8][4] = {};
#pragma unroll
        for (int kk = 0; kk < 8; kk++) {
            const int k = kk * 8 + 2 * tg;
            float2 qa = *(const float2*)&Qs[(wp * 16 + g) * QST + k];
            float2 qb = *(const float2*)&Qs[(wp * 16 + g + 8) * QST + k];
            unsigned a0 = FB(qa.x), a2 = FB(qa.y);
            unsigned a1 = FB(qb.x), a3 = FB(qb.y);
#pragma unroll
            for (int nt = 0; nt < 8; nt++) {
                float2 kf = *(const float2*)&Ks[(nt * 8 + g) * QST + k];
                mma_tf32(sc[nt], a0, a1, a2, a3, FB(kf.x), FB(kf.y));
            }
        }

        // ---- online softmax ----
        float mx0 = -1e30f, mx1 = -1e30f;
#pragma unroll
        for (int nt = 0; nt < 8; nt++) {
            mx0 = fmaxf(mx0, fmaxf(sc[nt][0], sc[nt][1]));
            mx1 = fmaxf(mx1, fmaxf(sc[nt][2], sc[nt][3]));
        }
#pragma unroll
        for (int off = 1; off <= 2; off <<= 1) {
            mx0 = fmaxf(mx0, __shfl_xor_sync(0xffffffffu, mx0, off));
            mx1 = fmaxf(mx1, __shfl_xor_sync(0xffffffffu, mx1, off));
        }
        float mn0 = fmaxf(mi[0], mx0), mn1 = fmaxf(mi[1], mx1);
        float al0 = __expf(mi[0] - mn0), al1 = __expf(mi[1] - mn1);
        mi[0] = mn0; mi[1] = mn1;
        float rs0 = 0.f, rs1 = 0.f;
#pragma unroll
        for (int nt = 0; nt < 8; nt++) {
            sc[nt][0] = __expf(sc[nt][0] - mn0);
            sc[nt][1] = __expf(sc[nt][1] - mn0);
            sc[nt][2] = __expf(sc[nt][2] - mn1);
            sc[nt][3] = __expf(sc[nt][3] - mn1);
            rs0 += sc[nt][0] + sc[nt][1];
            rs1 += sc[nt][2] + sc[nt][3];
        }
#pragma unroll
        for (int off = 1; off <= 2; off <<= 1) {
            rs0 += __shfl_xor_sync(0xffffffffu, rs0, off);
            rs1 += __shfl_xor_sync(0xffffffffu, rs1, off);
        }
        li[0] = li[0] * al0 + rs0;
        li[1] = li[1] * al1 + rs1;
#pragma unroll
        for (int nt = 0; nt < 8; nt++) {
            of[nt][0] *= al0; of[nt][1] *= al0;
            of[nt][2] *= al1; of[nt][3] *= al1;
        }

        // ---- store P (warp-private rows, natural layout) ----
#pragma unroll
        for (int nt = 0; nt < 8; nt++) {
            *(float2*)&Ps[(wp * 16 + g) * PST + nt * 8 + tg * 2] =
                make_float2(f2tf(sc[nt][0]), f2tf(sc[nt][1]));
            *(float2*)&Ps[(wp * 16 + g + 8) * PST + nt * 8 + tg * 2] =
                make_float2(f2tf(sc[nt][2]), f2tf(sc[nt][3]));
        }
        __syncwarp();

        // ---- prefetch next K/V tile ----
        {
            int kvn = (kv0 + 64 < SEQ) ? kv0 + 64 : 0;
            const float* ksrc = Kg + (size_t)(kvn + j) * DHEAD + seg;
            const float* vsrc = Vg + (size_t)(kvn + j) * DHEAD + seg;
#pragma unroll
            for (int i = 0; i < 4; i++) {
                pk[i] = *(const float4*)(ksrc + i * 4);
                pv[i] = *(const float4*)(vsrc + i * 4);
            }
        }

        // ---- O += P V ----
#pragma unroll
        for (int kk = 0; kk < 8; kk++) {
            const int k = kk * 8;
            const float* ap = &Ps[(wp * 16 + g) * PST + k + tg];
            unsigned a0 = FB(ap[0]), a1 = FB(ap[8 * PST]);
            unsigned a2 = FB(ap[4]), a3 = FB(ap[8 * PST + 4]);
            const int kv = k + 2 * tg;
#pragma unroll
            for (int nt = 0; nt < 8; nt++) {
                float2 vf = *(const float2*)&Vs[(nt * 8 + g) * QST + kv];
                mma_tf32(of[nt], a0, a1, a2, a3, FB(vf.x), FB(vf.y));
            }
        }
        __syncthreads();
    }

    // ---- epilogue ----
    const int b = bh >> 4;
    const int h = bh & 15;
    const float inv0 = 1.0f / li[0];
    const float inv1 = 1.0f / li[1];
    const int row0 = q0 + wp * 16 + g;
#pragma unroll
    for (int nt = 0; nt < 8; nt++) {
        int d = nt * 8 + tg * 2;
        *(float2*)&g_AO[((size_t)(b * SEQ + row0)) * DINNER + h * 64 + d] =
            make_float2(of[nt][0] * inv0, of[nt][1] * inv0);
        *(float2*)&g_AO[((size_t)(b * SEQ + row0 + 8)) * DINNER + h * 64 + d] =
            make_float2(of[nt][2] * inv1, of[nt][3] * inv1);
    }
}

// ---------------------------------------------------------------------
extern "C" void kernel_launch(void* const* d_in, const int* in_sizes, int n_in,
                              void* d_out, int out_size) {
    const float* x     = (const float*)d_in[0];
    const float* w_qkv = (const float*)d_in[1];
    const float* w_out = (const float*)d_in[2];
    const float* b_out = (const float*)d_in[3];
    float* out = (float*)d_out;

    cudaFuncSetAttribute(gemm_kernel, cudaFuncAttributeMaxDynamicSharedMemorySize,
                         GEMM_SMEM_BYTES);
    cudaFuncSetAttribute(attn_kernel, cudaFuncAttributeMaxDynamicSharedMemorySize,
                         ATTN_SMEM_BYTES);

    gemm_kernel<<<dim3(NQKV / 128, MROWS / 128), 256, GEMM_SMEM_BYTES>>>(x, w_qkv, nullptr, nullptr, 0);
    attn_kernel<<<dim3(SEQ / 128, BATCH * HEADS), 256, ATTN_SMEM_BYTES>>>();
    gemm_kernel<<<dim3(DSEQ / 128, MROWS / 128), 256, GEMM_SMEM_BYTES>>>(nullptr, w_out, b_out, out, 1);
}

// round 9
// speedup vs baseline: 1.1084x; 1.1084x over previous
#include <cuda_runtime.h>
#include <cstdint>

#define BATCH 4
#define SEQ   2048
#define DSEQ  1024
#define HEADS 16
#define DHEAD 64
#define DINNER 1024
#define MROWS (BATCH*SEQ)   // 8192
#define NQKV  (3*DINNER)    // 3072

// Scratch (allocation-free: __device__ globals)
__device__ float g_Q[BATCH * HEADS * SEQ * DHEAD];
__device__ float g_K[BATCH * HEADS * SEQ * DHEAD];
__device__ float g_V[BATCH * HEADS * SEQ * DHEAD];
__device__ float g_AO[MROWS * DINNER];
// tf32-pre-rounded operand copies
__device__ float g_X[MROWS * DSEQ];
__device__ float g_Wq[NQKV * DSEQ];
__device__ float g_Wo[DSEQ * DINNER];

__device__ __forceinline__ float f2tf(float f) {
    unsigned u;
    asm("cvt.rna.tf32.f32 %0, %1;" : "=r"(u) : "f"(f));
    return __uint_as_float(u);
}
__device__ __forceinline__ void mma_tf32(float c[4],
                                         unsigned a0, unsigned a1, unsigned a2, unsigned a3,
                                         unsigned b0, unsigned b1) {
    asm volatile(
        "mma.sync.aligned.m16n8k8.row.col.f32.tf32.tf32.f32 "
        "{%0,%1,%2,%3},{%4,%5,%6,%7},{%8,%9},{%0,%1,%2,%3};"
        : "+f"(c[0]), "+f"(c[1]), "+f"(c[2]), "+f"(c[3])
        : "r"(a0), "r"(a1), "r"(a2), "r"(a3), "r"(b0), "r"(b1));
}
#define FB(x) __float_as_uint(x)

__device__ __forceinline__ unsigned smem_u32(const void* p) {
    unsigned a;
    asm("{ .reg .u64 t; cvta.to.shared.u64 t, %1; cvt.u32.u64 %0, t; }"
        : "=r"(a) : "l"(p));
    return a;
}
__device__ __forceinline__ void cp16(unsigned dst, const float* src) {
    asm volatile("cp.async.cg.shared.global [%0], [%1], 16;"
                 :: "r"(dst), "l"(src) : "memory");
}
#define CP_COMMIT() asm volatile("cp.async.commit_group;" ::: "memory")
#define CP_WAIT2()  asm volatile("cp.async.wait_group 2;" ::: "memory")

// ---------------------------------------------------------------------
// Pre-convert inputs to tf32-rounded copies (rounding is idempotent).
// ---------------------------------------------------------------------
__global__ __launch_bounds__(256) void preconvert(const float* __restrict__ x,
                                                  const float* __restrict__ wq,
                                                  const float* __restrict__ wo) {
    const int idx = (blockIdx.x * 256 + threadIdx.x) * 4;
    const int NX = MROWS * DSEQ, NQ = NQKV * DSEQ, NO = DSEQ * DINNER;
    if (idx < NX) {
        float4 v = *(const float4*)(x + idx);
        *(float4*)(g_X + idx) = make_float4(f2tf(v.x), f2tf(v.y), f2tf(v.z), f2tf(v.w));
    } else if (idx < NX + NQ) {
        int i = idx - NX;
        float4 v = *(const float4*)(wq + i);
        *(float4*)(g_Wq + i) = make_float4(f2tf(v.x), f2tf(v.y), f2tf(v.z), f2tf(v.w));
    } else if (idx < NX + NQ + NO) {
        int i = idx - NX - NQ;
        float4 v = *(const float4*)(wo + i);
        *(float4*)(g_Wo + i) = make_float4(f2tf(v.x), f2tf(v.y), f2tf(v.z), f2tf(v.w));
    }
}
#define PRECONV_ELEMS (MROWS * DSEQ + NQKV * DSEQ + DSEQ * DINNER)

// ---------------------------------------------------------------------
// GEMM (round-7 structure): BM=BN=128, BK=16, 8 warps (2m x 4n), warp
// tile 64x32, GST=20 conflict-free, 4-stage cp.async (wait_group 2).
// Operands are PRE-ROUNDED -> inner loop is pure LDS + HMMA.
// mode 0: A=g_X, B=g_Wq, scatter tf32-rounded Q/K/V.
// mode 1: A=g_AO, B=g_Wo, out = D + bias.
// ---------------------------------------------------------------------
#define GST 20
#define NSTG 4
#define STGF (128 * GST)
#define GNIT 64
#define GEMM_SMEM_BYTES (2 * NSTG * STGF * 4)   // 81920

__device__ __forceinline__ void g_mma_tile(const float* As_, const float* Bs_,
                                           float c[4][4][4],
                                           int wm, int wn, int g, int tg) {
#pragma unroll
    for (int kk = 0; kk < 2; kk++) {
        const int k = kk * 8;
        unsigned a[4][4], b[4][2];
#pragma unroll
        for (int mt = 0; mt < 4; mt++) {
            const float* ap = &As_[(wm * 64 + mt * 16 + g) * GST + k + tg];
            a[mt][0] = FB(ap[0]);
            a[mt][1] = FB(ap[8 * GST]);
            a[mt][2] = FB(ap[4]);
            a[mt][3] = FB(ap[8 * GST + 4]);
        }
#pragma unroll
        for (int nt = 0; nt < 4; nt++) {
            const float* bp = &Bs_[(wn * 32 + nt * 8 + g) * GST + k + tg];
            b[nt][0] = FB(bp[0]);
            b[nt][1] = FB(bp[4]);
        }
#pragma unroll
        for (int mt = 0; mt < 4; mt++)
#pragma unroll
            for (int nt = 0; nt < 4; nt++)
                mma_tf32(c[mt][nt], a[mt][0], a[mt][1], a[mt][2], a[mt][3],
                         b[nt][0], b[nt][1]);
    }
}

__global__ __launch_bounds__(256, 2) void gemm_kernel(
    const float* __restrict__ bias, float* __restrict__ out, int mode)
{
    extern __shared__ float smf[];
    float* As = smf;
    float* Bs = smf + NSTG * STGF;

    const int t    = threadIdx.x;
    const int lane = t & 31;
    const int wp   = t >> 5;
    const int g    = lane >> 2;
    const int tg   = lane & 3;
    const int wm   = wp & 1;
    const int wn   = wp >> 1;
    const int m0   = blockIdx.y * 128;
    const int n0   = blockIdx.x * 128;

    const float* A = (mode == 1) ? (const float*)g_AO : (const float*)g_X;
    const float* B = (mode == 1) ? (const float*)g_Wo : (const float*)g_Wq;

    const int row  = t >> 1;
    const int half = (t & 1) * 8;
    const float* Ag = A + (size_t)(m0 + row) * 1024 + half;
    const float* Bg = B + (size_t)(n0 + row) * 1024 + half;
    const unsigned aOff = smem_u32(As) + (unsigned)(row * GST + half) * 4u;
    const unsigned bOff = smem_u32(Bs) + (unsigned)(row * GST + half) * 4u;

#pragma unroll
    for (int s = 0; s < 3; s++) {
        const int k0 = s * 16;
        const unsigned so = (unsigned)(s * STGF) * 4u;
        cp16(aOff + so,      Ag + k0);
        cp16(aOff + so + 16, Ag + k0 + 4);
        cp16(bOff + so,      Bg + k0);
        cp16(bOff + so + 16, Bg + k0 + 4);
        CP_COMMIT();
    }

    float c[4][4][4] = {};

    for (int it = 0; it < GNIT; it++) {
        CP_WAIT2();
        __syncthreads();
        if (it + 3 < GNIT) {
            const int k0 = (it + 3) * 16;
            const unsigned so = (unsigned)(((it + 3) & 3) * STGF) * 4u;
            cp16(aOff + so,      Ag + k0);
            cp16(aOff + so + 16, Ag + k0 + 4);
            cp16(bOff + so,      Bg + k0);
            cp16(bOff + so + 16, Bg + k0 + 4);
        }
        CP_COMMIT();
        const int cs = (it & 3) * STGF;
        g_mma_tile(As + cs, Bs + cs, c, wm, wn, g, tg);
    }

    if (mode == 0) {
        // scatter tf32-ROUNDED Q/K/V (removes cvts from attention)
#pragma unroll
        for (int mt = 0; mt < 4; mt++) {
#pragma unroll
            for (int nt = 0; nt < 4; nt++) {
                int col  = n0 + wn * 32 + nt * 8 + tg * 2;
                int part = col >> 10;
                int h    = (col >> 6) & 15;
                int d    = col & 63;
                float* Tp = (part == 0) ? g_Q : (part == 1) ? g_K : g_V;
                int m  = m0 + wm * 64 + mt * 16 + g;
                int b  = m >> 11, n = m & 2047;
                *(float2*)&Tp[(((size_t)(b * HEADS + h)) * SEQ + n) * DHEAD + d] =
                    make_float2(f2tf(c[mt][nt][0]), f2tf(c[mt][nt][1]));
                int m2 = m + 8;
                int b2 = m2 >> 11, n2 = m2 & 2047;
                *(float2*)&Tp[(((size_t)(b2 * HEADS + h)) * SEQ + n2) * DHEAD + d] =
                    make_float2(f2tf(c[mt][nt][2]), f2tf(c[mt][nt][3]));
            }
        }
    } else {
#pragma unroll
        for (int mt = 0; mt < 4; mt++) {
#pragma unroll
            for (int nt = 0; nt < 4; nt++) {
                int col = n0 + wn * 32 + nt * 8 + tg * 2;
                float bx = bias[col], by = bias[col + 1];
                int m = m0 + wm * 64 + mt * 16 + g;
                *(float2*)&out[(size_t)m * DSEQ + col] =
                    make_float2(c[mt][nt][0] + bx, c[mt][nt][1] + by);
                *(float2*)&out[(size_t)(m + 8) * DSEQ + col] =
                    make_float2(c[mt][nt][2] + bx, c[mt][nt][3] + by);
            }
        }
    }
}

// ---------------------------------------------------------------------
// Flash attention (round-5/7 verified layouts). Q/K/V arrive PRE-ROUNDED,
// so all store-path cvts are gone. P keeps f2tf after exp. Epilogue writes
// g_AO tf32-rounded so out_gemm needs no cvt.
// ---------------------------------------------------------------------
#define AST 68
#define ATTN_FLOATS ((128 + 64 + 64 + 128) * AST)
#define ATTN_SMEM_BYTES (ATTN_FLOATS * 4)

__global__ __launch_bounds__(256, 2) void attn_kernel() {
    extern __shared__ float sm[];
    float* Qs = sm;
    float* Ks = sm + 128 * AST;
    float* Vs = sm + 192 * AST;
    float* Ps = sm + 256 * AST;

    const int t    = threadIdx.x;
    const int lane = t & 31;
    const int wp   = t >> 5;
    const int g    = lane >> 2;
    const int tg   = lane & 3;
    const int bh   = blockIdx.y;
    const int q0   = blockIdx.x * 128;

    const size_t base = (size_t)bh * SEQ * DHEAD;
    const float* Qg = g_Q + base;
    const float* Kg = g_K + base;
    const float* Vg = g_V + base;

    // Q is pre-rounded tf32; x0.125 is exact (power of 2) -> still tf32
    {
        int row = t >> 1, h0 = (t & 1) * 32;
        const float* src = Qg + (size_t)(q0 + row) * DHEAD + h0;
        float* dst = &Qs[row * AST + h0];
#pragma unroll
        for (int i = 0; i < 8; i++) {
            float4 v = *(const float4*)(src + i * 4);
            *(float4*)(dst + i * 4) = make_float4(
                v.x * 0.125f, v.y * 0.125f, v.z * 0.125f, v.w * 0.125f);
        }
    }

    const int j   = t >> 2;
    const int seg = (t & 3) * 16;

    float4 pk[4], pv[4];
    {
        const float* ksrc = Kg + (size_t)j * DHEAD + seg;
        const float* vsrc = Vg + (size_t)j * DHEAD + seg;
#pragma unroll
        for (int i = 0; i < 4; i++) {
            pk[i] = *(const float4*)(ksrc + i * 4);
            pv[i] = *(const float4*)(vsrc + i * 4);
        }
    }

    float mi[2] = {-1e30f, -1e30f};
    float li[2] = {0.f, 0.f};
    float of[8][4] = {};

    for (int kv0 = 0; kv0 < SEQ; kv0 += 64) {
        {
            float* kd = &Ks[j * AST + seg];
#pragma unroll
            for (int i = 0; i < 4; i++) {
                *(float4*)(kd + i * 4) = pk[i];
                Vs[(seg + i * 4 + 0) * AST + j] = pv[i].x;
                Vs[(seg + i * 4 + 1) * AST + j] = pv[i].y;
                Vs[(seg + i * 4 + 2) * AST + j] = pv[i].z;
                Vs[(seg + i * 4 + 3) * AST + j] = pv[i].w;
            }
        }
        __syncthreads();

        float sc[8][4] = {};
#pragma unroll
        for (int kk = 0; kk < 8; kk++) {
            const int k = kk * 8;
            const float* ap = &Qs[(wp * 16 + g) * AST + k + tg];
            unsigned a0 = FB(ap[0]), a1 = FB(ap[8 * AST]);
            unsigned a2 = FB(ap[4]), a3 = FB(ap[8 * AST + 4]);
#pragma unroll
            for (int nt = 0; nt < 8; nt++) {
                const float* bp = &Ks[(nt * 8 + g) * AST + k + tg];
                mma_tf32(sc[nt], a0, a1, a2, a3, FB(bp[0]), FB(bp[4]));
            }
        }

        float mx0 = -1e30f, mx1 = -1e30f;
#pragma unroll
        for (int nt = 0; nt < 8; nt++) {
            mx0 = fmaxf(mx0, fmaxf(sc[nt][0], sc[nt][1]));
            mx1 = fmaxf(mx1, fmaxf(sc[nt][2], sc[nt][3]));
        }
#pragma unroll
        for (int off = 1; off <= 2; off <<= 1) {
            mx0 = fmaxf(mx0, __shfl_xor_sync(0xffffffffu, mx0, off));
            mx1 = fmaxf(mx1, __shfl_xor_sync(0xffffffffu, mx1, off));
        }
        float mn0 = fmaxf(mi[0], mx0), mn1 = fmaxf(mi[1], mx1);
        float al0 = __expf(mi[0] - mn0), al1 = __expf(mi[1] - mn1);
        mi[0] = mn0; mi[1] = mn1;
        float rs0 = 0.f, rs1 = 0.f;
#pragma unroll
        for (int nt = 0; nt < 8; nt++) {
            sc[nt][0] = __expf(sc[nt][0] - mn0);
            sc[nt][1] = __expf(sc[nt][1] - mn0);
            sc[nt][2] = __expf(sc[nt][2] - mn1);
            sc[nt][3] = __expf(sc[nt][3] - mn1);
            rs0 += sc[nt][0] + sc[nt][1];
            rs1 += sc[nt][2] + sc[nt][3];
        }
#pragma unroll
        for (int off = 1; off <= 2; off <<= 1) {
            rs0 += __shfl_xor_sync(0xffffffffu, rs0, off);
            rs1 += __shfl_xor_sync(0xffffffffu, rs1, off);
        }
        li[0] = li[0] * al0 + rs0;
        li[1] = li[1] * al1 + rs1;
#pragma unroll
        for (int nt = 0; nt < 8; nt++) {
            of[nt][0] *= al0; of[nt][1] *= al0;
            of[nt][2] *= al1; of[nt][3] *= al1;
        }

#pragma unroll
        for (int nt = 0; nt < 8; nt++) {
            *(float2*)&Ps[(wp * 16 + g) * AST + nt * 8 + tg * 2] =
                make_float2(f2tf(sc[nt][0]), f2tf(sc[nt][1]));
            *(float2*)&Ps[(wp * 16 + g + 8) * AST + nt * 8 + tg * 2] =
                make_float2(f2tf(sc[nt][2]), f2tf(sc[nt][3]));
        }
        __syncwarp();

        {
            int kvn = (kv0 + 64 < SEQ) ? kv0 + 64 : 0;
            const float* ksrc = Kg + (size_t)(kvn + j) * DHEAD + seg;
            const float* vsrc = Vg + (size_t)(kvn + j) * DHEAD + seg;
#pragma unroll
            for (int i = 0; i < 4; i++) {
                pk[i] = *(const float4*)(ksrc + i * 4);
                pv[i] = *(const float4*)(vsrc + i * 4);
            }
        }

#pragma unroll
        for (int kk = 0; kk < 8; kk++) {
            const int k = kk * 8;
            const float* ap = &Ps[(wp * 16 + g) * AST + k + tg];
            unsigned a0 = FB(ap[0]), a1 = FB(ap[8 * AST]);
            unsigned a2 = FB(ap[4]), a3 = FB(ap[8 * AST + 4]);
#pragma unroll
            for (int nt = 0; nt < 8; nt++) {
                const float* bp = &Vs[(nt * 8 + g) * AST + k + tg];
                mma_tf32(of[nt], a0, a1, a2, a3, FB(bp[0]), FB(bp[4]));
            }
        }
        __syncthreads();
    }

    // write g_AO tf32-ROUNDED (out_gemm A-side needs no cvt)
    const int b = bh >> 4;
    const int h = bh & 15;
    const float inv0 = 1.0f / li[0];
    const float inv1 = 1.0f / li[1];
    const int row0 = q0 + wp * 16 + g;
#pragma unroll
    for (int nt = 0; nt < 8; nt++) {
        int d = nt * 8 + tg * 2;
        *(float2*)&g_AO[((size_t)(b * SEQ + row0)) * DINNER + h * 64 + d] =
            make_float2(f2tf(of[nt][0] * inv0), f2tf(of[nt][1] * inv0));
        *(float2*)&g_AO[((size_t)(b * SEQ + row0 + 8)) * DINNER + h * 64 + d] =
            make_float2(f2tf(of[nt][2] * inv1), f2tf(of[nt][3] * inv1));
    }
}

// ---------------------------------------------------------------------
extern "C" void kernel_launch(void* const* d_in, const int* in_sizes, int n_in,
                              void* d_out, int out_size) {
    const float* x     = (const float*)d_in[0];
    const float* w_qkv = (const float*)d_in[1];
    const float* w_out = (const float*)d_in[2];
    const float* b_out = (const float*)d_in[3];
    float* out = (float*)d_out;

    cudaFuncSetAttribute(gemm_kernel, cudaFuncAttributeMaxDynamicSharedMemorySize,
                         GEMM_SMEM_BYTES);
    cudaFuncSetAttribute(attn_kernel, cudaFuncAttributeMaxDynamicSharedMemorySize,
                         ATTN_SMEM_BYTES);

    preconvert<<<(PRECONV_ELEMS / 4 + 255) / 256, 256>>>(x, w_qkv, w_out);
    gemm_kernel<<<dim3(NQKV / 128, MROWS / 128), 256, GEMM_SMEM_BYTES>>>(nullptr, nullptr, 0);
    attn_kernel<<<dim3(SEQ / 128, BATCH * HEADS), 256, ATTN_SMEM_BYTES>>>();
    gemm_kernel<<<dim3(DSEQ / 128, MROWS / 128), 256, GEMM_SMEM_BYTES>>>(b_out, out, 1);
}

// round 10
// speedup vs baseline: 1.2099x; 1.0916x over previous
#include <cuda_runtime.h>
#include <cstdint>

#define BATCH 4
#define SEQ   2048
#define DSEQ  1024
#define HEADS 16
#define DHEAD 64
#define DINNER 1024
#define MROWS (BATCH*SEQ)   // 8192
#define NQKV  (3*DINNER)    // 3072

// Scratch (allocation-free: __device__ globals)
__device__ float g_Q[BATCH * HEADS * SEQ * DHEAD];
__device__ float g_K[BATCH * HEADS * SEQ * DHEAD];
__device__ float g_V[BATCH * HEADS * SEQ * DHEAD];
__device__ float g_AO[MROWS * DINNER];
// tf32-pre-rounded operand copies
__device__ float g_X[MROWS * DSEQ];
__device__ float g_Wq[NQKV * DSEQ];
__device__ float g_Wo[DSEQ * DINNER];

__device__ __forceinline__ float f2tf(float f) {
    unsigned u;
    asm("cvt.rna.tf32.f32 %0, %1;" : "=r"(u) : "f"(f));
    return __uint_as_float(u);
}
__device__ __forceinline__ void mma_tf32(float c[4],
                                         unsigned a0, unsigned a1, unsigned a2, unsigned a3,
                                         unsigned b0, unsigned b1) {
    asm volatile(
        "mma.sync.aligned.m16n8k8.row.col.f32.tf32.tf32.f32 "
        "{%0,%1,%2,%3},{%4,%5,%6,%7},{%8,%9},{%0,%1,%2,%3};"
        : "+f"(c[0]), "+f"(c[1]), "+f"(c[2]), "+f"(c[3])
        : "r"(a0), "r"(a1), "r"(a2), "r"(a3), "r"(b0), "r"(b1));
}
#define FB(x) __float_as_uint(x)

__device__ __forceinline__ unsigned smem_u32(const void* p) {
    unsigned a;
    asm("{ .reg .u64 t; cvta.to.shared.u64 t, %1; cvt.u32.u64 %0, t; }"
        : "=r"(a) : "l"(p));
    return a;
}
__device__ __forceinline__ void cp16(unsigned dst, const float* src) {
    asm volatile("cp.async.cg.shared.global [%0], [%1], 16;"
                 :: "r"(dst), "l"(src) : "memory");
}
#define CP_COMMIT() asm volatile("cp.async.commit_group;" ::: "memory")
#define CP_WAIT2()  asm volatile("cp.async.wait_group 2;" ::: "memory")
#define CP_WAIT1()  asm volatile("cp.async.wait_group 1;" ::: "memory")

// ---------------------------------------------------------------------
// Pre-convert inputs to tf32-rounded copies.
// ---------------------------------------------------------------------
__global__ __launch_bounds__(256) void preconvert(const float* __restrict__ x,
                                                  const float* __restrict__ wq,
                                                  const float* __restrict__ wo) {
    const int idx = (blockIdx.x * 256 + threadIdx.x) * 4;
    const int NX = MROWS * DSEQ, NQ = NQKV * DSEQ, NO = DSEQ * DINNER;
    if (idx < NX) {
        float4 v = *(const float4*)(x + idx);
        *(float4*)(g_X + idx) = make_float4(f2tf(v.x), f2tf(v.y), f2tf(v.z), f2tf(v.w));
    } else if (idx < NX + NQ) {
        int i = idx - NX;
        float4 v = *(const float4*)(wq + i);
        *(float4*)(g_Wq + i) = make_float4(f2tf(v.x), f2tf(v.y), f2tf(v.z), f2tf(v.w));
    } else if (idx < NX + NQ + NO) {
        int i = idx - NX - NQ;
        float4 v = *(const float4*)(wo + i);
        *(float4*)(g_Wo + i) = make_float4(f2tf(v.x), f2tf(v.y), f2tf(v.z), f2tf(v.w));
    }
}
#define PRECONV_ELEMS (MROWS * DSEQ + NQKV * DSEQ + DSEQ * DINNER)

// ---------------------------------------------------------------------
// GEMM (round-9, verified): BM=BN=128, BK=16, 8 warps, GST=20, 4-stage
// cp.async. mode 0: g_X @ g_Wq^T -> Q/K/V.  mode 1: g_AO @ g_Wo^T + bias.
// ---------------------------------------------------------------------
#define GST 20
#define NSTG 4
#define STGF (128 * GST)
#define GNIT 64
#define GEMM_SMEM_BYTES (2 * NSTG * STGF * 4)   // 81920

__device__ __forceinline__ void g_mma_tile(const float* As_, const float* Bs_,
                                           float c[4][4][4],
                                           int wm, int wn, int g, int tg) {
#pragma unroll
    for (int kk = 0; kk < 2; kk++) {
        const int k = kk * 8;
        unsigned a[4][4], b[4][2];
#pragma unroll
        for (int mt = 0; mt < 4; mt++) {
            const float* ap = &As_[(wm * 64 + mt * 16 + g) * GST + k + tg];
            a[mt][0] = FB(ap[0]);
            a[mt][1] = FB(ap[8 * GST]);
            a[mt][2] = FB(ap[4]);
            a[mt][3] = FB(ap[8 * GST + 4]);
        }
#pragma unroll
        for (int nt = 0; nt < 4; nt++) {
            const float* bp = &Bs_[(wn * 32 + nt * 8 + g) * GST + k + tg];
            b[nt][0] = FB(bp[0]);
            b[nt][1] = FB(bp[4]);
        }
#pragma unroll
        for (int mt = 0; mt < 4; mt++)
#pragma unroll
            for (int nt = 0; nt < 4; nt++)
                mma_tf32(c[mt][nt], a[mt][0], a[mt][1], a[mt][2], a[mt][3],
                         b[nt][0], b[nt][1]);
    }
}

__global__ __launch_bounds__(256, 2) void gemm_kernel(
    const float* __restrict__ bias, float* __restrict__ out, int mode)
{
    extern __shared__ float smf[];
    float* As = smf;
    float* Bs = smf + NSTG * STGF;

    const int t    = threadIdx.x;
    const int lane = t & 31;
    const int wp   = t >> 5;
    const int g    = lane >> 2;
    const int tg   = lane & 3;
    const int wm   = wp & 1;
    const int wn   = wp >> 1;
    const int m0   = blockIdx.y * 128;
    const int n0   = blockIdx.x * 128;

    const float* A = (mode == 1) ? (const float*)g_AO : (const float*)g_X;
    const float* B = (mode == 1) ? (const float*)g_Wo : (const float*)g_Wq;

    const int row  = t >> 1;
    const int half = (t & 1) * 8;
    const float* Ag = A + (size_t)(m0 + row) * 1024 + half;
    const float* Bg = B + (size_t)(n0 + row) * 1024 + half;
    const unsigned aOff = smem_u32(As) + (unsigned)(row * GST + half) * 4u;
    const unsigned bOff = smem_u32(Bs) + (unsigned)(row * GST + half) * 4u;

#pragma unroll
    for (int s = 0; s < 3; s++) {
        const int k0 = s * 16;
        const unsigned so = (unsigned)(s * STGF) * 4u;
        cp16(aOff + so,      Ag + k0);
        cp16(aOff + so + 16, Ag + k0 + 4);
        cp16(bOff + so,      Bg + k0);
        cp16(bOff + so + 16, Bg + k0 + 4);
        CP_COMMIT();
    }

    float c[4][4][4] = {};

    for (int it = 0; it < GNIT; it++) {
        CP_WAIT2();
        __syncthreads();
        if (it + 3 < GNIT) {
            const int k0 = (it + 3) * 16;
            const unsigned so = (unsigned)(((it + 3) & 3) * STGF) * 4u;
            cp16(aOff + so,      Ag + k0);
            cp16(aOff + so + 16, Ag + k0 + 4);
            cp16(bOff + so,      Bg + k0);
            cp16(bOff + so + 16, Bg + k0 + 4);
        }
        CP_COMMIT();
        const int cs = (it & 3) * STGF;
        g_mma_tile(As + cs, Bs + cs, c, wm, wn, g, tg);
    }

    if (mode == 0) {
#pragma unroll
        for (int mt = 0; mt < 4; mt++) {
#pragma unroll
            for (int nt = 0; nt < 4; nt++) {
                int col  = n0 + wn * 32 + nt * 8 + tg * 2;
                int part = col >> 10;
                int h    = (col >> 6) & 15;
                int d    = col & 63;
                float* Tp = (part == 0) ? g_Q : (part == 1) ? g_K : g_V;
                int m  = m0 + wm * 64 + mt * 16 + g;
                int b  = m >> 11, n = m & 2047;
                *(float2*)&Tp[(((size_t)(b * HEADS + h)) * SEQ + n) * DHEAD + d] =
                    make_float2(f2tf(c[mt][nt][0]), f2tf(c[mt][nt][1]));
                int m2 = m + 8;
                int b2 = m2 >> 11, n2 = m2 & 2047;
                *(float2*)&Tp[(((size_t)(b2 * HEADS + h)) * SEQ + n2) * DHEAD + d] =
                    make_float2(f2tf(c[mt][nt][2]), f2tf(c[mt][nt][3]));
            }
        }
    } else {
#pragma unroll
        for (int mt = 0; mt < 4; mt++) {
#pragma unroll
            for (int nt = 0; nt < 4; nt++) {
                int col = n0 + wn * 32 + nt * 8 + tg * 2;
                float bx = bias[col], by = bias[col + 1];
                int m = m0 + wm * 64 + mt * 16 + g;
                *(float2*)&out[(size_t)m * DSEQ + col] =
                    make_float2(c[mt][nt][0] + bx, c[mt][nt][1] + by);
                *(float2*)&out[(size_t)(m + 8) * DSEQ + col] =
                    make_float2(c[mt][nt][2] + bx, c[mt][nt][3] + by);
            }
        }
    }
}

// ---------------------------------------------------------------------
// Flash attention v2: 128 threads (4 warps), each warp 32 query rows
// (2 m16 tiles) -> LDS/HMMA drops 2.5 -> 1.5. kv-tile 64.
// Qs[128][68] natural | Ks[64][68] natural [j][d] | Vs[64][72] natural
// [j][d] (B-frags read strided, conflict-free at 72) | Ps[128][68].
// K/V loaded via cp.async, single buffer, split waits:
//   K(i+1) issued after S-phase, V(i+1) after PV; ledger = [K,V].
// ---------------------------------------------------------------------
#define AQT 68
#define AVT 72
#define ATTN_FLOATS (128*AQT + 64*AQT + 64*AVT + 128*AQT)
#define ATTN_SMEM_BYTES (ATTN_FLOATS * 4)   // 105472

__global__ __launch_bounds__(128, 2) void attn_kernel() {
    extern __shared__ float sm[];
    float* Qs = sm;                               // 128*68
    float* Ks = sm + 128 * AQT;                   // 64*68
    float* Vs = sm + 128 * AQT + 64 * AQT;        // 64*72
    float* Ps = sm + 128 * AQT + 64 * AQT + 64 * AVT;  // 128*68

    const int t    = threadIdx.x;
    const int lane = t & 31;
    const int wp   = t >> 5;        // 0..3, owns rows wp*32..wp*32+31
    const int g    = lane >> 2;
    const int tg   = lane & 3;
    const int bh   = blockIdx.y;
    const int q0   = blockIdx.x * 128;

    const size_t base = (size_t)bh * SEQ * DHEAD;
    const float* Qg = g_Q + base;
    const float* Kg = g_K + base;
    const float* Vg = g_V + base;

    // cp.async loader mapping: thread -> row t>>1, 32-float half (t&1)*32
    const int lj = t >> 1;
    const int lh = (t & 1) * 32;
    const unsigned kDst = smem_u32(Ks) + (unsigned)(lj * AQT + lh) * 4u;
    const unsigned vDst = smem_u32(Vs) + (unsigned)(lj * AVT + lh) * 4u;
    const float* kSrc = Kg + (size_t)lj * DHEAD + lh;
    const float* vSrc = Vg + (size_t)lj * DHEAD + lh;

    // prologue: K0, V0 in flight
#pragma unroll
    for (int q = 0; q < 8; q++) cp16(kDst + q * 16u, kSrc + q * 4);
    CP_COMMIT();
#pragma unroll
    for (int q = 0; q < 8; q++) cp16(vDst + q * 16u, vSrc + q * 4);
    CP_COMMIT();

    // Q tile (pre-rounded tf32; x0.125 exact)
    {
        const float* src = Qg + (size_t)(q0 + t) * DHEAD;
        float* dst = &Qs[t * AQT];
#pragma unroll
        for (int i = 0; i < 16; i++) {
            float4 v = *(const float4*)(src + i * 4);
            *(float4*)(dst + i * 4) = make_float4(
                v.x * 0.125f, v.y * 0.125f, v.z * 0.125f, v.w * 0.125f);
        }
    }

    float mi[4] = {-1e30f, -1e30f, -1e30f, -1e30f};
    float li[4] = {0.f, 0.f, 0.f, 0.f};
    float of[2][8][4] = {};

    for (int i = 0; i < SEQ / 64; i++) {
        CP_WAIT1();          // K_i complete (V_i may be in flight)
        __syncthreads();     // K_i (and Q on i=0) visible to all warps

        // ---- S = Q K^T : warp rows wp*32 (2 m-tiles), all 64 cols ----
        float sc[2][8][4] = {};
#pragma unroll
        for (int kk = 0; kk < 8; kk++) {
            const int k = kk * 8;
            unsigned a[2][4];
#pragma unroll
            for (int mt = 0; mt < 2; mt++) {
                const float* ap = &Qs[(wp * 32 + mt * 16 + g) * AQT + k + tg];
                a[mt][0] = FB(ap[0]);
                a[mt][1] = FB(ap[8 * AQT]);
                a[mt][2] = FB(ap[4]);
                a[mt][3] = FB(ap[8 * AQT + 4]);
            }
#pragma unroll
            for (int nt = 0; nt < 8; nt++) {
                const float* bp = &Ks[(nt * 8 + g) * AQT + k + tg];
                unsigned b0 = FB(bp[0]), b1 = FB(bp[4]);
                mma_tf32(sc[0][nt], a[0][0], a[0][1], a[0][2], a[0][3], b0, b1);
                mma_tf32(sc[1][nt], a[1][0], a[1][1], a[1][2], a[1][3], b0, b1);
            }
        }
        __syncthreads();     // all warps done reading K_i

        // ---- issue K_{i+1} (overlaps softmax + PV) ----
        if (i + 1 < SEQ / 64) {
            const float* ks = kSrc + (size_t)(i + 1) * 64 * DHEAD;
#pragma unroll
            for (int q = 0; q < 8; q++) cp16(kDst + q * 16u, ks + q * 4);
        }
        CP_COMMIT();

        // ---- online softmax: 4 row-sets (mt*16 + {g, g+8}) ----
        float mx[4] = {-1e30f, -1e30f, -1e30f, -1e30f};
#pragma unroll
        for (int mt = 0; mt < 2; mt++)
#pragma unroll
            for (int nt = 0; nt < 8; nt++) {
                mx[2*mt]   = fmaxf(mx[2*mt],   fmaxf(sc[mt][nt][0], sc[mt][nt][1]));
                mx[2*mt+1] = fmaxf(mx[2*mt+1], fmaxf(sc[mt][nt][2], sc[mt][nt][3]));
            }
#pragma unroll
        for (int off = 1; off <= 2; off <<= 1)
#pragma unroll
            for (int r = 0; r < 4; r++)
                mx[r] = fmaxf(mx[r], __shfl_xor_sync(0xffffffffu, mx[r], off));
        float al[4], rs[4] = {0.f, 0.f, 0.f, 0.f};
#pragma unroll
        for (int r = 0; r < 4; r++) {
            float mn = fmaxf(mi[r], mx[r]);
            al[r] = __expf(mi[r] - mn);
            mi[r] = mn;
        }
#pragma unroll
        for (int mt = 0; mt < 2; mt++)
#pragma unroll
            for (int nt = 0; nt < 8; nt++) {
                sc[mt][nt][0] = __expf(sc[mt][nt][0] - mi[2*mt]);
                sc[mt][nt][1] = __expf(sc[mt][nt][1] - mi[2*mt]);
                sc[mt][nt][2] = __expf(sc[mt][nt][2] - mi[2*mt+1]);
                sc[mt][nt][3] = __expf(sc[mt][nt][3] - mi[2*mt+1]);
                rs[2*mt]   += sc[mt][nt][0] + sc[mt][nt][1];
                rs[2*mt+1] += sc[mt][nt][2] + sc[mt][nt][3];
            }
#pragma unroll
        for (int off = 1; off <= 2; off <<= 1)
#pragma unroll
            for (int r = 0; r < 4; r++)
                rs[r] += __shfl_xor_sync(0xffffffffu, rs[r], off);
#pragma unroll
        for (int r = 0; r < 4; r++) li[r] = li[r] * al[r] + rs[r];
#pragma unroll
        for (int mt = 0; mt < 2; mt++)
#pragma unroll
            for (int nt = 0; nt < 8; nt++) {
                of[mt][nt][0] *= al[2*mt];   of[mt][nt][1] *= al[2*mt];
                of[mt][nt][2] *= al[2*mt+1]; of[mt][nt][3] *= al[2*mt+1];
            }

        CP_WAIT1();          // V_i complete (K_{i+1} may be in flight)
        __syncthreads();     // V_i visible

        // ---- store P (warp-private rows) ----
#pragma unroll
        for (int mt = 0; mt < 2; mt++)
#pragma unroll
            for (int nt = 0; nt < 8; nt++) {
                *(float2*)&Ps[(wp * 32 + mt * 16 + g) * AQT + nt * 8 + tg * 2] =
                    make_float2(f2tf(sc[mt][nt][0]), f2tf(sc[mt][nt][1]));
                *(float2*)&Ps[(wp * 32 + mt * 16 + g + 8) * AQT + nt * 8 + tg * 2] =
                    make_float2(f2tf(sc[mt][nt][2]), f2tf(sc[mt][nt][3]));
            }
        __syncwarp();

        // ---- O += P V  (V natural [j][d]: B-frag = strided reads) ----
#pragma unroll
        for (int kk = 0; kk < 8; kk++) {
            const int k = kk * 8;
            unsigned a[2][4];
#pragma unroll
            for (int mt = 0; mt < 2; mt++) {
                const float* ap = &Ps[(wp * 32 + mt * 16 + g) * AQT + k + tg];
                a[mt][0] = FB(ap[0]);
                a[mt][1] = FB(ap[8 * AQT]);
                a[mt][2] = FB(ap[4]);
                a[mt][3] = FB(ap[8 * AQT + 4]);
            }
#pragma unroll
            for (int nt = 0; nt < 8; nt++) {
                unsigned b0 = FB(Vs[(k + tg)     * AVT + nt * 8 + g]);
                unsigned b1 = FB(Vs[(k + tg + 4) * AVT + nt * 8 + g]);
                mma_tf32(of[0][nt], a[0][0], a[0][1], a[0][2], a[0][3], b0, b1);
                mma_tf32(of[1][nt], a[1][0], a[1][1], a[1][2], a[1][3], b0, b1);
            }
        }
        __syncthreads();     // all warps done reading V_i

        // ---- issue V_{i+1} ----
        if (i + 1 < SEQ / 64) {
            const float* vs = vSrc + (size_t)(i + 1) * 64 * DHEAD;
#pragma unroll
            for (int q = 0; q < 8; q++) cp16(vDst + q * 16u, vs + q * 4);
        }
        CP_COMMIT();
    }

    // ---- epilogue: write g_AO tf32-rounded ----
    const int b = bh >> 4;
    const int h = bh & 15;
#pragma unroll
    for (int mt = 0; mt < 2; mt++) {
        const float inv0 = 1.0f / li[2*mt];
        const float inv1 = 1.0f / li[2*mt+1];
        const int row0 = q0 + wp * 32 + mt * 16 + g;
#pragma unroll
        for (int nt = 0; nt < 8; nt++) {
            int d = nt * 8 + tg * 2;
            *(float2*)&g_AO[((size_t)(b * SEQ + row0)) * DINNER + h * 64 + d] =
                make_float2(f2tf(of[mt][nt][0] * inv0), f2tf(of[mt][nt][1] * inv0));
            *(float2*)&g_AO[((size_t)(b * SEQ + row0 + 8)) * DINNER + h * 64 + d] =
                make_float2(f2tf(of[mt][nt][2] * inv1), f2tf(of[mt][nt][3] * inv1));
        }
    }
}

// ---------------------------------------------------------------------
extern "C" void kernel_launch(void* const* d_in, const int* in_sizes, int n_in,
                              void* d_out, int out_size) {
    const float* x     = (const float*)d_in[0];
    const float* w_qkv = (const float*)d_in[1];
    const float* w_out = (const float*)d_in[2];
    const float* b_out = (const float*)d_in[3];
    float* out = (float*)d_out;

    cudaFuncSetAttribute(gemm_kernel, cudaFuncAttributeMaxDynamicSharedMemorySize,
                         GEMM_SMEM_BYTES);
    cudaFuncSetAttribute(attn_kernel, cudaFuncAttributeMaxDynamicSharedMemorySize,
                         ATTN_SMEM_BYTES);

    preconvert<<<(PRECONV_ELEMS / 4 + 255) / 256, 256>>>(x, w_qkv, w_out);
    gemm_kernel<<<dim3(NQKV / 128, MROWS / 128), 256, GEMM_SMEM_BYTES>>>(nullptr, nullptr, 0);
    attn_kernel<<<dim3(SEQ / 128, BATCH * HEADS), 128, ATTN_SMEM_BYTES>>>();
    gemm_kernel<<<dim3(DSEQ / 128, MROWS / 128), 256, GEMM_SMEM_BYTES>>>(b_out, out, 1);
}

// round 11
// speedup vs baseline: 1.2822x; 1.0597x over previous
#include <cuda_runtime.h>
#include <cstdint>

#define BATCH 4
#define SEQ   2048
#define DSEQ  1024
#define HEADS 16
#define DHEAD 64
#define DINNER 1024
#define MROWS (BATCH*SEQ)   // 8192
#define NQKV  (3*DINNER)    // 3072

// Scratch (allocation-free: __device__ globals)
__device__ float g_Q[BATCH * HEADS * SEQ * DHEAD];
__device__ float g_K[BATCH * HEADS * SEQ * DHEAD];
__device__ float g_V[BATCH * HEADS * SEQ * DHEAD];
__device__ float g_AO[MROWS * DINNER];
// tf32-pre-rounded operand copies
__device__ float g_X[MROWS * DSEQ];
__device__ float g_Wq[NQKV * DSEQ];
__device__ float g_Wo[DSEQ * DINNER];

__device__ __forceinline__ float f2tf(float f) {
    unsigned u;
    asm("cvt.rna.tf32.f32 %0, %1;" : "=r"(u) : "f"(f));
    return __uint_as_float(u);
}
__device__ __forceinline__ void mma_tf32(float c[4],
                                         unsigned a0, unsigned a1, unsigned a2, unsigned a3,
                                         unsigned b0, unsigned b1) {
    asm volatile(
        "mma.sync.aligned.m16n8k8.row.col.f32.tf32.tf32.f32 "
        "{%0,%1,%2,%3},{%4,%5,%6,%7},{%8,%9},{%0,%1,%2,%3};"
        : "+f"(c[0]), "+f"(c[1]), "+f"(c[2]), "+f"(c[3])
        : "r"(a0), "r"(a1), "r"(a2), "r"(a3), "r"(b0), "r"(b1));
}
#define FB(x) __float_as_uint(x)

__device__ __forceinline__ unsigned smem_u32(const void* p) {
    unsigned a;
    asm("{ .reg .u64 t; cvta.to.shared.u64 t, %1; cvt.u32.u64 %0, t; }"
        : "=r"(a) : "l"(p));
    return a;
}
__device__ __forceinline__ void cp16(unsigned dst, const float* src) {
    asm volatile("cp.async.cg.shared.global [%0], [%1], 16;"
                 :: "r"(dst), "l"(src) : "memory");
}
#define CP_COMMIT() asm volatile("cp.async.commit_group;" ::: "memory")
#define CP_WAIT2()  asm volatile("cp.async.wait_group 2;" ::: "memory")
#define CP_WAIT1()  asm volatile("cp.async.wait_group 1;" ::: "memory")

// ---------------------------------------------------------------------
// Pre-convert inputs to tf32-rounded copies.
// ---------------------------------------------------------------------
__global__ __launch_bounds__(256) void preconvert(const float* __restrict__ x,
                                                  const float* __restrict__ wq,
                                                  const float* __restrict__ wo) {
    const int idx = (blockIdx.x * 256 + threadIdx.x) * 4;
    const int NX = MROWS * DSEQ, NQ = NQKV * DSEQ, NO = DSEQ * DINNER;
    if (idx < NX) {
        float4 v = *(const float4*)(x + idx);
        *(float4*)(g_X + idx) = make_float4(f2tf(v.x), f2tf(v.y), f2tf(v.z), f2tf(v.w));
    } else if (idx < NX + NQ) {
        int i = idx - NX;
        float4 v = *(const float4*)(wq + i);
        *(float4*)(g_Wq + i) = make_float4(f2tf(v.x), f2tf(v.y), f2tf(v.z), f2tf(v.w));
    } else if (idx < NX + NQ + NO) {
        int i = idx - NX - NQ;
        float4 v = *(const float4*)(wo + i);
        *(float4*)(g_Wo + i) = make_float4(f2tf(v.x), f2tf(v.y), f2tf(v.z), f2tf(v.w));
    }
}
#define PRECONV_ELEMS (MROWS * DSEQ + NQKV * DSEQ + DSEQ * DINNER)

// ---------------------------------------------------------------------
// GEMM v2: BM=BN=128, BK=16, 512 threads = 16 warps (4m x 4n), warp tile
// 32x32 (accum 32 regs -> 2 CTAs, 8 warps/SMSP). GST=20 conflict-free,
// 4-stage cp.async (wait_group 2).
// mode 0: g_X @ g_Wq^T -> scatter tf32-rounded Q/K/V.
// mode 1: g_AO @ g_Wo^T + bias -> out.
// ---------------------------------------------------------------------
#define GST 20
#define NSTG 4
#define STGF (128 * GST)
#define GNIT 64
#define GEMM_SMEM_BYTES (2 * NSTG * STGF * 4)   // 81920

__device__ __forceinline__ void g_mma_tile(const float* As_, const float* Bs_,
                                           float c[2][4][4],
                                           int wm, int wn, int g, int tg) {
#pragma unroll
    for (int kk = 0; kk < 2; kk++) {
        const int k = kk * 8;
        unsigned a[2][4], b[4][2];
#pragma unroll
        for (int mt = 0; mt < 2; mt++) {
            const float* ap = &As_[(wm * 32 + mt * 16 + g) * GST + k + tg];
            a[mt][0] = FB(ap[0]);
            a[mt][1] = FB(ap[8 * GST]);
            a[mt][2] = FB(ap[4]);
            a[mt][3] = FB(ap[8 * GST + 4]);
        }
#pragma unroll
        for (int nt = 0; nt < 4; nt++) {
            const float* bp = &Bs_[(wn * 32 + nt * 8 + g) * GST + k + tg];
            b[nt][0] = FB(bp[0]);
            b[nt][1] = FB(bp[4]);
        }
#pragma unroll
        for (int mt = 0; mt < 2; mt++)
#pragma unroll
            for (int nt = 0; nt < 4; nt++)
                mma_tf32(c[mt][nt], a[mt][0], a[mt][1], a[mt][2], a[mt][3],
                         b[nt][0], b[nt][1]);
    }
}

__global__ __launch_bounds__(512, 2) void gemm_kernel(
    const float* __restrict__ bias, float* __restrict__ out, int mode)
{
    extern __shared__ float smf[];
    float* As = smf;
    float* Bs = smf + NSTG * STGF;

    const int t    = threadIdx.x;
    const int lane = t & 31;
    const int wp   = t >> 5;        // 0..15
    const int g    = lane >> 2;
    const int tg   = lane & 3;
    const int wm   = wp & 3;        // 0..3  (m quarter, 32 rows)
    const int wn   = wp >> 2;       // 0..3  (n quarter, 32 cols)
    const int m0   = blockIdx.y * 128;
    const int n0   = blockIdx.x * 128;

    const float* A = (mode == 1) ? (const float*)g_AO : (const float*)g_X;
    const float* B = (mode == 1) ? (const float*)g_Wo : (const float*)g_Wq;

    // loader: thread -> row t>>2 (0..127), k-quad (t&3)*4; 1 cp16/matrix/stage
    const int row = t >> 2;
    const int kq  = (t & 3) * 4;
    const float* Ag = A + (size_t)(m0 + row) * 1024 + kq;
    const float* Bg = B + (size_t)(n0 + row) * 1024 + kq;
    const unsigned aOff = smem_u32(As) + (unsigned)(row * GST + kq) * 4u;
    const unsigned bOff = smem_u32(Bs) + (unsigned)(row * GST + kq) * 4u;

#pragma unroll
    for (int s = 0; s < 3; s++) {
        const unsigned so = (unsigned)(s * STGF) * 4u;
        cp16(aOff + so, Ag + s * 16);
        cp16(bOff + so, Bg + s * 16);
        CP_COMMIT();
    }

    float c[2][4][4] = {};

    for (int it = 0; it < GNIT; it++) {
        CP_WAIT2();
        __syncthreads();
        if (it + 3 < GNIT) {
            const unsigned so = (unsigned)(((it + 3) & 3) * STGF) * 4u;
            cp16(aOff + so, Ag + (it + 3) * 16);
            cp16(bOff + so, Bg + (it + 3) * 16);
        }
        CP_COMMIT();
        const int cs = (it & 3) * STGF;
        g_mma_tile(As + cs, Bs + cs, c, wm, wn, g, tg);
    }

    if (mode == 0) {
#pragma unroll
        for (int mt = 0; mt < 2; mt++) {
#pragma unroll
            for (int nt = 0; nt < 4; nt++) {
                int col  = n0 + wn * 32 + nt * 8 + tg * 2;
                int part = col >> 10;
                int h    = (col >> 6) & 15;
                int d    = col & 63;
                float* Tp = (part == 0) ? g_Q : (part == 1) ? g_K : g_V;
                int m  = m0 + wm * 32 + mt * 16 + g;
                int b  = m >> 11, n = m & 2047;
                *(float2*)&Tp[(((size_t)(b * HEADS + h)) * SEQ + n) * DHEAD + d] =
                    make_float2(f2tf(c[mt][nt][0]), f2tf(c[mt][nt][1]));
                int m2 = m + 8;
                int b2 = m2 >> 11, n2 = m2 & 2047;
                *(float2*)&Tp[(((size_t)(b2 * HEADS + h)) * SEQ + n2) * DHEAD + d] =
                    make_float2(f2tf(c[mt][nt][2]), f2tf(c[mt][nt][3]));
            }
        }
    } else {
#pragma unroll
        for (int mt = 0; mt < 2; mt++) {
#pragma unroll
            for (int nt = 0; nt < 4; nt++) {
                int col = n0 + wn * 32 + nt * 8 + tg * 2;
                float bx = bias[col], by = bias[col + 1];
                int m = m0 + wm * 32 + mt * 16 + g;
                *(float2*)&out[(size_t)m * DSEQ + col] =
                    make_float2(c[mt][nt][0] + bx, c[mt][nt][1] + by);
                *(float2*)&out[(size_t)(m + 8) * DSEQ + col] =
                    make_float2(c[mt][nt][2] + bx, c[mt][nt][3] + by);
            }
        }
    }
}

// ---------------------------------------------------------------------
// Flash attention (round-10, verified; unchanged): 128 threads (4 warps),
// warp = 32 query rows, kv-tile 64, cp.async K/V split waits.
// ---------------------------------------------------------------------
#define AQT 68
#define AVT 72
#define ATTN_FLOATS (128*AQT + 64*AQT + 64*AVT + 128*AQT)
#define ATTN_SMEM_BYTES (ATTN_FLOATS * 4)   // 105472

__global__ __launch_bounds__(128, 2) void attn_kernel() {
    extern __shared__ float sm[];
    float* Qs = sm;
    float* Ks = sm + 128 * AQT;
    float* Vs = sm + 128 * AQT + 64 * AQT;
    float* Ps = sm + 128 * AQT + 64 * AQT + 64 * AVT;

    const int t    = threadIdx.x;
    const int lane = t & 31;
    const int wp   = t >> 5;
    const int g    = lane >> 2;
    const int tg   = lane & 3;
    const int bh   = blockIdx.y;
    const int q0   = blockIdx.x * 128;

    const size_t base = (size_t)bh * SEQ * DHEAD;
    const float* Qg = g_Q + base;
    const float* Kg = g_K + base;
    const float* Vg = g_V + base;

    const int lj = t >> 1;
    const int lh = (t & 1) * 32;
    const unsigned kDst = smem_u32(Ks) + (unsigned)(lj * AQT + lh) * 4u;
    const unsigned vDst = smem_u32(Vs) + (unsigned)(lj * AVT + lh) * 4u;
    const float* kSrc = Kg + (size_t)lj * DHEAD + lh;
    const float* vSrc = Vg + (size_t)lj * DHEAD + lh;

#pragma unroll
    for (int q = 0; q < 8; q++) cp16(kDst + q * 16u, kSrc + q * 4);
    CP_COMMIT();
#pragma unroll
    for (int q = 0; q < 8; q++) cp16(vDst + q * 16u, vSrc + q * 4);
    CP_COMMIT();

    {
        const float* src = Qg + (size_t)(q0 + t) * DHEAD;
        float* dst = &Qs[t * AQT];
#pragma unroll
        for (int i = 0; i < 16; i++) {
            float4 v = *(const float4*)(src + i * 4);
            *(float4*)(dst + i * 4) = make_float4(
                v.x * 0.125f, v.y * 0.125f, v.z * 0.125f, v.w * 0.125f);
        }
    }

    float mi[4] = {-1e30f, -1e30f, -1e30f, -1e30f};
    float li[4] = {0.f, 0.f, 0.f, 0.f};
    float of[2][8][4] = {};

    for (int i = 0; i < SEQ / 64; i++) {
        CP_WAIT1();
        __syncthreads();

        float sc[2][8][4] = {};
#pragma unroll
        for (int kk = 0; kk < 8; kk++) {
            const int k = kk * 8;
            unsigned a[2][4];
#pragma unroll
            for (int mt = 0; mt < 2; mt++) {
                const float* ap = &Qs[(wp * 32 + mt * 16 + g) * AQT + k + tg];
                a[mt][0] = FB(ap[0]);
                a[mt][1] = FB(ap[8 * AQT]);
                a[mt][2] = FB(ap[4]);
                a[mt][3] = FB(ap[8 * AQT + 4]);
            }
#pragma unroll
            for (int nt = 0; nt < 8; nt++) {
                const float* bp = &Ks[(nt * 8 + g) * AQT + k + tg];
                unsigned b0 = FB(bp[0]), b1 = FB(bp[4]);
                mma_tf32(sc[0][nt], a[0][0], a[0][1], a[0][2], a[0][3], b0, b1);
                mma_tf32(sc[1][nt], a[1][0], a[1][1], a[1][2], a[1][3], b0, b1);
            }
        }
        __syncthreads();

        if (i + 1 < SEQ / 64) {
            const float* ks = kSrc + (size_t)(i + 1) * 64 * DHEAD;
#pragma unroll
            for (int q = 0; q < 8; q++) cp16(kDst + q * 16u, ks + q * 4);
        }
        CP_COMMIT();

        float mx[4] = {-1e30f, -1e30f, -1e30f, -1e30f};
#pragma unroll
        for (int mt = 0; mt < 2; mt++)
#pragma unroll
            for (int nt = 0; nt < 8; nt++) {
                mx[2*mt]   = fmaxf(mx[2*mt],   fmaxf(sc[mt][nt][0], sc[mt][nt][1]));
                mx[2*mt+1] = fmaxf(mx[2*mt+1], fmaxf(sc[mt][nt][2], sc[mt][nt][3]));
            }
#pragma unroll
        for (int off = 1; off <= 2; off <<= 1)
#pragma unroll
            for (int r = 0; r < 4; r++)
                mx[r] = fmaxf(mx[r], __shfl_xor_sync(0xffffffffu, mx[r], off));
        float al[4], rs[4] = {0.f, 0.f, 0.f, 0.f};
#pragma unroll
        for (int r = 0; r < 4; r++) {
            float mn = fmaxf(mi[r], mx[r]);
            al[r] = __expf(mi[r] - mn);
            mi[r] = mn;
        }
#pragma unroll
        for (int mt = 0; mt < 2; mt++)
#pragma unroll
            for (int nt = 0; nt < 8; nt++) {
                sc[mt][nt][0] = __expf(sc[mt][nt][0] - mi[2*mt]);
                sc[mt][nt][1] = __expf(sc[mt][nt][1] - mi[2*mt]);
                sc[mt][nt][2] = __expf(sc[mt][nt][2] - mi[2*mt+1]);
                sc[mt][nt][3] = __expf(sc[mt][nt][3] - mi[2*mt+1]);
                rs[2*mt]   += sc[mt][nt][0] + sc[mt][nt][1];
                rs[2*mt+1] += sc[mt][nt][2] + sc[mt][nt][3];
            }
#pragma unroll
        for (int off = 1; off <= 2; off <<= 1)
#pragma unroll
            for (int r = 0; r < 4; r++)
                rs[r] += __shfl_xor_sync(0xffffffffu, rs[r], off);
#pragma unroll
        for (int r = 0; r < 4; r++) li[r] = li[r] * al[r] + rs[r];
#pragma unroll
        for (int mt = 0; mt < 2; mt++)
#pragma unroll
            for (int nt = 0; nt < 8; nt++) {
                of[mt][nt][0] *= al[2*mt];   of[mt][nt][1] *= al[2*mt];
                of[mt][nt][2] *= al[2*mt+1]; of[mt][nt][3] *= al[2*mt+1];
            }

        CP_WAIT1();
        __syncthreads();

#pragma unroll
        for (int mt = 0; mt < 2; mt++)
#pragma unroll
            for (int nt = 0; nt < 8; nt++) {
                *(float2*)&Ps[(wp * 32 + mt * 16 + g) * AQT + nt * 8 + tg * 2] =
                    make_float2(f2tf(sc[mt][nt][0]), f2tf(sc[mt][nt][1]));
                *(float2*)&Ps[(wp * 32 + mt * 16 + g + 8) * AQT + nt * 8 + tg * 2] =
                    make_float2(f2tf(sc[mt][nt][2]), f2tf(sc[mt][nt][3]));
            }
        __syncwarp();

#pragma unroll
        for (int kk = 0; kk < 8; kk++) {
            const int k = kk * 8;
            unsigned a[2][4];
#pragma unroll
            for (int mt = 0; mt < 2; mt++) {
                const float* ap = &Ps[(wp * 32 + mt * 16 + g) * AQT + k + tg];
                a[mt][0] = FB(ap[0]);
                a[mt][1] = FB(ap[8 * AQT]);
                a[mt][2] = FB(ap[4]);
                a[mt][3] = FB(ap[8 * AQT + 4]);
            }
#pragma unroll
            for (int nt = 0; nt < 8; nt++) {
                unsigned b0 = FB(Vs[(k + tg)     * AVT + nt * 8 + g]);
                unsigned b1 = FB(Vs[(k + tg + 4) * AVT + nt * 8 + g]);
                mma_tf32(of[0][nt], a[0][0], a[0][1], a[0][2], a[0][3], b0, b1);
                mma_tf32(of[1][nt], a[1][0], a[1][1], a[1][2], a[1][3], b0, b1);
            }
        }
        __syncthreads();

        if (i + 1 < SEQ / 64) {
            const float* vs = vSrc + (size_t)(i + 1) * 64 * DHEAD;
#pragma unroll
            for (int q = 0; q < 8; q++) cp16(vDst + q * 16u, vs + q * 4);
        }
        CP_COMMIT();
    }

    const int b = bh >> 4;
    const int h = bh & 15;
#pragma unroll
    for (int mt = 0; mt < 2; mt++) {
        const float inv0 = 1.0f / li[2*mt];
        const float inv1 = 1.0f / li[2*mt+1];
        const int row0 = q0 + wp * 32 + mt * 16 + g;
#pragma unroll
        for (int nt = 0; nt < 8; nt++) {
            int d = nt * 8 + tg * 2;
            *(float2*)&g_AO[((size_t)(b * SEQ + row0)) * DINNER + h * 64 + d] =
                make_float2(f2tf(of[mt][nt][0] * inv0), f2tf(of[mt][nt][1] * inv0));
            *(float2*)&g_AO[((size_t)(b * SEQ + row0 + 8)) * DINNER + h * 64 + d] =
                make_float2(f2tf(of[mt][nt][2] * inv1), f2tf(of[mt][nt][3] * inv1));
        }
    }
}

// ---------------------------------------------------------------------
extern "C" void kernel_launch(void* const* d_in, const int* in_sizes, int n_in,
                              void* d_out, int out_size) {
    const float* x     = (const float*)d_in[0];
    const float* w_qkv = (const float*)d_in[1];
    const float* w_out = (const float*)d_in[2];
    const float* b_out = (const float*)d_in[3];
    float* out = (float*)d_out;

    cudaFuncSetAttribute(gemm_kernel, cudaFuncAttributeMaxDynamicSharedMemorySize,
                         GEMM_SMEM_BYTES);
    cudaFuncSetAttribute(attn_kernel, cudaFuncAttributeMaxDynamicSharedMemorySize,
                         ATTN_SMEM_BYTES);

    preconvert<<<(PRECONV_ELEMS / 4 + 255) / 256, 256>>>(x, w_qkv, w_out);
    gemm_kernel<<<dim3(NQKV / 128, MROWS / 128), 512, GEMM_SMEM_BYTES>>>(nullptr, nullptr, 0);
    attn_kernel<<<dim3(SEQ / 128, BATCH * HEADS), 128, ATTN_SMEM_BYTES>>>();
    gemm_kernel<<<dim3(DSEQ / 128, MROWS / 128), 512, GEMM_SMEM_BYTES>>>(b_out, out, 1);
}